// round 1
// baseline (speedup 1.0000x reference)
#include <cuda_runtime.h>
#include <math.h>

// Problem constants
#define BB   1024
#define NN   100
#define HH   128
#define NHD  8
#define HDD  16
#define STEPS 128
#define NEGV -1000000000.0f
#define NPAD 132          // padded stride for N x H smem tiles (bank-conflict free)

// -------- device scratch (static __device__ arrays; no cudaMalloc allowed) ----
__device__ float g_K [BB*NN*HH];   // enc @ Wk^T        (B,N,H)
__device__ float g_V [BB*NN*HH];   // enc @ Wv^T
__device__ float g_K2[BB*NN*HH];   // enc @ (Wk2^T Wo) * inv_sqrt_H
__device__ float g_Qe[BB*NN*HH];   // enc @ (0.25 * Wq fc_w[:, :128])^T
__device__ float g_qpool[BB*HH];   // 0.25 * (pool @ fc1_w^T) @ Wq^T
__device__ float g_Wqf[HH*(HH+1)]; // 0.25 * Wq @ fc_w   (128 x 129)
__device__ float g_WfoldT[HH*HH];  // transposed fold:  WfoldT[c][m] = invsH * sum_i Wk2[i][m]*Wo[i][c]
__device__ float g_Wpq[HH*HH];     // 0.25 * Wq @ fc1_w

// ======================= fold kernel (tiny) =================================
__global__ void fold_kernel(const float* __restrict__ fc_w,
                            const float* __restrict__ fc1_w,
                            const float* __restrict__ Wq,
                            const float* __restrict__ Wo,
                            const float* __restrict__ Wk2)
{
    int mat = blockIdx.y;
    int r   = blockIdx.x;       // 0..127
    int j   = threadIdx.x;      // 0..131
    if (mat == 0) {             // Wqf[r][j] = 0.25 * sum_i Wq[r,i] * fc_w[i,j], j<129
        if (j < 129) {
            float acc = 0.f;
            #pragma unroll 8
            for (int i = 0; i < 128; i++) acc += Wq[r*128 + i] * fc_w[i*129 + j];
            g_Wqf[r*129 + j] = 0.25f * acc;
        }
    } else if (mat == 1) {      // WfoldT[r][j] = invsH * sum_i Wk2[i,j] * Wo[i,r]
        if (j < 128) {
            float acc = 0.f;
            #pragma unroll 8
            for (int i = 0; i < 128; i++) acc += Wk2[i*128 + j] * Wo[i*128 + r];
            g_WfoldT[r*128 + j] = (1.0f / sqrtf(128.0f)) * acc;
        }
    } else {                    // Wpq[r][j] = 0.25 * sum_i Wq[r,i] * fc1_w[i,j]
        if (j < 128) {
            float acc = 0.f;
            #pragma unroll 8
            for (int i = 0; i < 128; i++) acc += Wq[r*128 + i] * fc1_w[i*128 + j];
            g_Wpq[r*128 + j] = 0.25f * acc;
        }
    }
}

// ======================= GEMM: out = A @ W^T ================================
// 5 slices via blockIdx.y:
//  0: enc  @ Wk^T      -> g_K
//  1: enc  @ Wv^T      -> g_V
//  2: enc  @ WfoldT^T  -> g_K2
//  3: enc  @ Wqf^T     -> g_Qe   (ldw = 129, first 128 cols)
//  4: pool @ Wpq^T     -> g_qpool
#define GM_TILE 64
#define GEMM_SMEM ((128*132 + GM_TILE*132) * 4)

__global__ __launch_bounds__(256) void gemm_kernel(const float* __restrict__ enc,
                                                   const float* __restrict__ pool,
                                                   const float* __restrict__ Wk,
                                                   const float* __restrict__ Wv)
{
    extern __shared__ float sm[];
    float* sW = sm;                 // [128][132]  layout sW[m*132 + c] = W[c][m]
    float* sA = sm + 128*132;       // [64][132]

    int slice = blockIdx.y;
    const float* A; const float* W; float* O; int rows; int ldw = 128;
    if      (slice == 0) { A = enc;  W = Wk;       O = g_K;     rows = BB*NN; }
    else if (slice == 1) { A = enc;  W = Wv;       O = g_V;     rows = BB*NN; }
    else if (slice == 2) { A = enc;  W = g_WfoldT; O = g_K2;    rows = BB*NN; }
    else if (slice == 3) { A = enc;  W = g_Wqf;    O = g_Qe;    rows = BB*NN; ldw = 129; }
    else                 { A = pool; W = g_Wpq;    O = g_qpool; rows = BB;    }

    int row0 = blockIdx.x * GM_TILE;
    if (row0 >= rows) return;
    int tid = threadIdx.x;

    for (int i = tid; i < 128*128; i += 256) {
        int c = i >> 7, m = i & 127;
        sW[m*132 + c] = W[c*ldw + m];
    }
    for (int i = tid; i < GM_TILE*128; i += 256) {
        int r = i >> 7, k = i & 127;
        sA[r*132 + k] = A[(row0 + r)*128 + k];
    }
    __syncthreads();

    int warp = tid >> 5, lane = tid & 31;
    int r0 = warp * 8, c0 = lane * 4;
    float acc[8][4];
    #pragma unroll
    for (int i = 0; i < 8; i++) { acc[i][0]=0; acc[i][1]=0; acc[i][2]=0; acc[i][3]=0; }

    #pragma unroll 4
    for (int k = 0; k < 128; k++) {
        float4 w4 = *(const float4*)&sW[k*132 + c0];
        #pragma unroll
        for (int i = 0; i < 8; i++) {
            float a = sA[(r0 + i)*132 + k];
            acc[i][0] += a * w4.x;
            acc[i][1] += a * w4.y;
            acc[i][2] += a * w4.z;
            acc[i][3] += a * w4.w;
        }
    }
    #pragma unroll
    for (int i = 0; i < 8; i++) {
        float4 v; v.x = acc[i][0]; v.y = acc[i][1]; v.z = acc[i][2]; v.w = acc[i][3];
        *(float4*)&O[(size_t)(row0 + r0 + i)*128 + c0] = v;
    }
}

// ======================= decode kernel ======================================
// 1 CTA per batch row b; 256 threads; all per-row state in smem; 128 serial steps.
#define DEC_SMEM_FLOATS (4*NN*NPAD + 800 + 104 + 100 + 100 + 100 + 128*4 + 256)
#define DEC_SMEM (DEC_SMEM_FLOATS * 4)

__global__ __launch_bounds__(256) void decode_kernel(const float* __restrict__ capacity,
                                                     const float* __restrict__ demand,
                                                     float* __restrict__ out)
{
    extern __shared__ float sm[];
    float* sK    = sm;                    // [100][132]
    float* sV    = sK  + NN*NPAD;
    float* sK2   = sV  + NN*NPAD;
    float* sQe   = sK2 + NN*NPAD;
    float* sAttn = sQe + NN*NPAD;         // [8][100]
    float* sU    = sAttn + 800;           // 100 (pad 104)
    float* sDem  = sU    + 104;           // 100
    float* sMask = sDem  + 100;           // 100
    float* sMask1= sMask + 100;           // 100
    float* sQ    = sMask1+ 100;           // 128
    float* sG    = sQ    + 128;           // 128
    float* sQp   = sG    + 128;           // 128
    float* sWc   = sQp   + 128;           // 128
    float* sPart = sWc   + 128;           // 256

    __shared__ float sCap, sLog;
    __shared__ int   sIdx, sVis, sCnt;

    int b = blockIdx.x, tid = threadIdx.x;

    // ---- load per-row tiles (float4, padded smem stride) ----
    {
        const float4* gK  = (const float4*)(g_K  + (size_t)b*NN*HH);
        const float4* gV  = (const float4*)(g_V  + (size_t)b*NN*HH);
        const float4* gK2 = (const float4*)(g_K2 + (size_t)b*NN*HH);
        const float4* gQe = (const float4*)(g_Qe + (size_t)b*NN*HH);
        for (int j = tid; j < NN*HH/4; j += 256) {
            int n = j >> 5; int c = (j & 31) << 2; int d = n*NPAD + c;
            *(float4*)&sK [d] = gK [j];
            *(float4*)&sV [d] = gV [j];
            *(float4*)&sK2[d] = gK2[j];
            *(float4*)&sQe[d] = gQe[j];
        }
    }
    if (tid < 100) sDem[tid] = demand[b*NN + tid];
    if (tid < 128) {
        sQp[tid] = g_qpool[b*HH + tid];
        sWc[tid] = g_Wqf[tid*129 + 128];
    }
    if (tid == 0) { sCap = capacity[b]; sIdx = 0; sVis = 0; sLog = 0.f; sCnt = 0; }
    __syncthreads();

    // ---- initial mask (update_mask with index=0, mask1=0) ----
    {
        float c0 = sCap;
        if (tid < 100) {
            sMask1[tid] = 0.f;
            float m = (sDem[tid] > c0) ? 1.f : 0.f;
            sMask[tid] = m;
            if (tid >= 1 && m == 0.f) atomicAdd(&sCnt, 1);
        }
    }
    __syncthreads();
    if (tid == 0) sMask[0] = (sCnt == 0) ? 0.f : 1.f;  // go_depot = true initially
    __syncthreads();

    const float base_cap = capacity[0];

    for (int s = 0; s < STEPS; s++) {
        // ---- q = Qenc[idx] + Wc*cap + qpool (0.25 and Wq,fc_w folded) ----
        if (tid < 128) sQ[tid] = sQe[sIdx*NPAD + tid] + sWc[tid]*sCap + sQp[tid];
        __syncthreads();

        // ---- scores (masked) ----
        for (int i = tid; i < 800; i += 256) {
            int h = i / 100, n = i - h*100;
            float v;
            if (sMask[n] > 0.f) v = NEGV;
            else {
                const float4* kp = (const float4*)&sK[n*NPAD + h*HDD];
                const float4* qp = (const float4*)&sQ[h*HDD];
                float4 a0=kp[0], a1=kp[1], a2=kp[2], a3=kp[3];
                float4 b0=qp[0], b1=qp[1], b2=qp[2], b3=qp[3];
                v = a0.x*b0.x + a0.y*b0.y + a0.z*b0.z + a0.w*b0.w
                  + a1.x*b1.x + a1.y*b1.y + a1.z*b1.z + a1.w*b1.w
                  + a2.x*b2.x + a2.y*b2.y + a2.z*b2.z + a2.w*b2.w
                  + a3.x*b3.x + a3.y*b3.y + a3.z*b3.z + a3.w*b3.w;
            }
            sAttn[i] = v;
        }
        __syncthreads();

        // ---- softmax per head (warp h owns head h) ----
        {
            int h = tid >> 5, ln = tid & 31;
            float* row = sAttn + h*100;
            float m = -INFINITY;
            for (int n = ln; n < 100; n += 32) m = fmaxf(m, row[n]);
            #pragma unroll
            for (int o = 16; o; o >>= 1) m = fmaxf(m, __shfl_xor_sync(0xffffffffu, m, o));
            float sum = 0.f;
            for (int n = ln; n < 100; n += 32) { float e = expf(row[n] - m); row[n] = e; sum += e; }
            #pragma unroll
            for (int o = 16; o; o >>= 1) sum += __shfl_xor_sync(0xffffffffu, sum, o);
            for (int n = ln; n < 100; n += 32) row[n] = row[n] / sum;
        }
        __syncthreads();

        // ---- glimpse g[d] = sum_n attn[h(d),n] * V[n,d]  (split n in halves) ----
        {
            int p = tid & 127, half = tid >> 7;
            int h = p >> 4;
            const float* an = sAttn + h*100 + half*50;
            const float* vp = sV + (half*50)*NPAD + p;
            float acc = 0.f;
            #pragma unroll 10
            for (int n = 0; n < 50; n++) acc += an[n] * vp[n*NPAD];
            sPart[tid] = acc;
        }
        __syncthreads();
        if (tid < 128) sG[tid] = sPart[tid] + sPart[tid + 128];
        __syncthreads();

        // ---- u[n] = 10*tanh(K2'[n] . g)  (Wo and 1/sqrt(H) folded; split j) ----
        {
            int p = tid & 127, half = tid >> 7;
            if (p < 100) {
                const float* kp = sK2 + p*NPAD + half*64;
                const float* gp = sG + half*64;
                float acc = 0.f;
                #pragma unroll
                for (int j = 0; j < 64; j += 4) {
                    float4 a = *(const float4*)&kp[j];
                    float4 g = *(const float4*)&gp[j];
                    acc += a.x*g.x + a.y*g.y + a.z*g.z + a.w*g.w;
                }
                sPart[tid] = acc;
            }
        }
        __syncthreads();
        if (tid < 100) {
            float t = sPart[tid] + sPart[tid + 128];
            sU[tid] = (sMask[tid] > 0.f) ? NEGV : 10.0f * tanhf(t);
        }
        __syncthreads();

        // ---- argmax (first-index ties) + log-softmax value; state update ----
        if (tid < 32) {
            float vmax = -INFINITY; int imax = 0;
            for (int n = tid; n < 100; n += 32) {
                float v = sU[n];
                if (v > vmax) { vmax = v; imax = n; }
            }
            #pragma unroll
            for (int o = 16; o; o >>= 1) {
                float ov = __shfl_down_sync(0xffffffffu, vmax, o);
                int   oi = __shfl_down_sync(0xffffffffu, imax, o);
                if (ov > vmax || (ov == vmax && oi < imax)) { vmax = ov; imax = oi; }
            }
            vmax = __shfl_sync(0xffffffffu, vmax, 0);
            imax = __shfl_sync(0xffffffffu, imax, 0);
            float sum = 0.f;
            for (int n = tid; n < 100; n += 32) sum += expf(sU[n] - vmax);
            #pragma unroll
            for (int o = 16; o; o >>= 1) sum += __shfl_xor_sync(0xffffffffu, sum, o);
            if (tid == 0) {
                float logp = -logf(sum);                 // u[argmax]-max == 0
                if (sVis < 99) sLog += logp;             // is_done gating (pre-update mask1)
                out[(size_t)b*STEPS + s] = (float)imax;  // actions.T[b, s]
                float seld = sDem[imax];
                sCap = (imax == 0) ? base_cap : (sCap - seld);
                sIdx = imax;
                if (imax > 0 && sMask1[imax] == 0.f) { sMask1[imax] = 1.f; sVis += 1; }
                sCnt = 0;
            }
        }
        __syncthreads();

        // ---- update_mask(cap, index, mask1) ----
        if (tid >= 1 && tid < 100) {
            float m = fmaxf(sMask1[tid], (sDem[tid] > sCap) ? 1.f : 0.f);
            sMask[tid] = m;
            if (m == 0.f) atomicAdd(&sCnt, 1);
        }
        __syncthreads();
        if (tid == 0) sMask[0] = (sCnt == 0) ? 0.f : ((sIdx == 0) ? 1.f : 0.f);
        __syncthreads();
    }

    if (tid == 0) out[(size_t)BB*STEPS + b] = sLog;
}

// ======================= launcher ===========================================
extern "C" void kernel_launch(void* const* d_in, const int* in_sizes, int n_in,
                              void* d_out, int out_size)
{
    const float* enc      = (const float*)d_in[0];
    const float* pool     = (const float*)d_in[1];
    const float* capacity = (const float*)d_in[2];
    const float* demand   = (const float*)d_in[3];
    const float* fc_w     = (const float*)d_in[4];
    const float* fc1_w    = (const float*)d_in[5];
    const float* Wq       = (const float*)d_in[6];
    const float* Wk       = (const float*)d_in[7];
    const float* Wv       = (const float*)d_in[8];
    // d_in[9] = Wo, d_in[10] = Wk2 (used in fold only)
    const float* Wo       = (const float*)d_in[9];
    const float* Wk2      = (const float*)d_in[10];
    float* out = (float*)d_out;

    cudaFuncSetAttribute(gemm_kernel,   cudaFuncAttributeMaxDynamicSharedMemorySize, GEMM_SMEM);
    cudaFuncSetAttribute(decode_kernel, cudaFuncAttributeMaxDynamicSharedMemorySize, DEC_SMEM);

    fold_kernel<<<dim3(128, 3), 132>>>(fc_w, fc1_w, Wq, Wo, Wk2);
    gemm_kernel<<<dim3((BB*NN)/GM_TILE, 5), 256, GEMM_SMEM>>>(enc, pool, Wk, Wv);
    decode_kernel<<<BB, 256, DEC_SMEM>>>(capacity, demand, out);
}

// round 2
// speedup vs baseline: 1.5746x; 1.5746x over previous
#include <cuda_runtime.h>
#include <math.h>

// Problem constants
#define BB   1024
#define NN   100
#define HH   128
#define STEPS 128
#define NEGV -1000000000.0f
#define NPAD 132          // padded stride (16B-aligned, conflict-free)

// -------- device scratch ----
__device__ float g_K [BB*NN*HH];   // enc @ Wk^T        (B,N,H)
__device__ float g_V [BB*NN*HH];   // enc @ Wv^T
__device__ float g_K2[BB*NN*HH];   // enc @ (Wk2^T Wo) * inv_sqrt_H
__device__ float g_Qe[BB*NN*HH];   // enc @ (0.25 * Wq fc_w[:, :128])^T
__device__ float g_qpool[BB*HH];   // 0.25 * (pool @ fc1_w^T) @ Wq^T
__device__ float g_Wqf[HH*(HH+1)]; // 0.25 * Wq @ fc_w   (128 x 129)
__device__ float g_WfoldT[HH*HH];  // WfoldT[c][m] = invsH * sum_i Wk2[i][m]*Wo[i][c]
__device__ float g_Wpq[HH*HH];     // 0.25 * Wq @ fc1_w

// ======================= fold kernel (tiny) =================================
__global__ void fold_kernel(const float* __restrict__ fc_w,
                            const float* __restrict__ fc1_w,
                            const float* __restrict__ Wq,
                            const float* __restrict__ Wo,
                            const float* __restrict__ Wk2)
{
    int mat = blockIdx.y;
    int r   = blockIdx.x;       // 0..127
    int j   = threadIdx.x;      // 0..131
    if (mat == 0) {
        if (j < 129) {
            float acc = 0.f;
            #pragma unroll 8
            for (int i = 0; i < 128; i++) acc += Wq[r*128 + i] * fc_w[i*129 + j];
            g_Wqf[r*129 + j] = 0.25f * acc;
        }
    } else if (mat == 1) {
        if (j < 128) {
            float acc = 0.f;
            #pragma unroll 8
            for (int i = 0; i < 128; i++) acc += Wk2[i*128 + j] * Wo[i*128 + r];
            g_WfoldT[r*128 + j] = (1.0f / sqrtf(128.0f)) * acc;
        }
    } else {
        if (j < 128) {
            float acc = 0.f;
            #pragma unroll 8
            for (int i = 0; i < 128; i++) acc += Wq[r*128 + i] * fc1_w[i*128 + j];
            g_Wpq[r*128 + j] = 0.25f * acc;
        }
    }
}

// ======================= GEMM: out = A @ W^T ================================
#define GM_TILE 64
#define GEMM_SMEM ((128*132 + GM_TILE*132) * 4)

__global__ __launch_bounds__(256) void gemm_kernel(const float* __restrict__ enc,
                                                   const float* __restrict__ pool,
                                                   const float* __restrict__ Wk,
                                                   const float* __restrict__ Wv)
{
    extern __shared__ float sm[];
    float* sW = sm;                 // [128][132]  sW[m*132 + c] = W[c][m]
    float* sA = sm + 128*132;       // [64][132]

    int slice = blockIdx.y;
    const float* A; const float* W; float* O; int rows; int ldw = 128;
    if      (slice == 0) { A = enc;  W = Wk;       O = g_K;     rows = BB*NN; }
    else if (slice == 1) { A = enc;  W = Wv;       O = g_V;     rows = BB*NN; }
    else if (slice == 2) { A = enc;  W = g_WfoldT; O = g_K2;    rows = BB*NN; }
    else if (slice == 3) { A = enc;  W = g_Wqf;    O = g_Qe;    rows = BB*NN; ldw = 129; }
    else                 { A = pool; W = g_Wpq;    O = g_qpool; rows = BB;    }

    int row0 = blockIdx.x * GM_TILE;
    if (row0 >= rows) return;
    int tid = threadIdx.x;

    for (int i = tid; i < 128*128; i += 256) {
        int c = i >> 7, m = i & 127;
        sW[m*132 + c] = W[c*ldw + m];
    }
    for (int i = tid; i < GM_TILE*128; i += 256) {
        int r = i >> 7, k = i & 127;
        sA[r*132 + k] = A[(row0 + r)*128 + k];
    }
    __syncthreads();

    int warp = tid >> 5, lane = tid & 31;
    int r0 = warp * 8, c0 = lane * 4;
    float acc[8][4];
    #pragma unroll
    for (int i = 0; i < 8; i++) { acc[i][0]=0; acc[i][1]=0; acc[i][2]=0; acc[i][3]=0; }

    #pragma unroll 4
    for (int k = 0; k < 128; k++) {
        float4 w4 = *(const float4*)&sW[k*132 + c0];
        #pragma unroll
        for (int i = 0; i < 8; i++) {
            float a = sA[(r0 + i)*132 + k];
            acc[i][0] += a * w4.x;
            acc[i][1] += a * w4.y;
            acc[i][2] += a * w4.z;
            acc[i][3] += a * w4.w;
        }
    }
    #pragma unroll
    for (int i = 0; i < 8; i++) {
        float4 v; v.x = acc[i][0]; v.y = acc[i][1]; v.z = acc[i][2]; v.w = acc[i][3];
        *(float4*)&O[(size_t)(row0 + r0 + i)*128 + c0] = v;
    }
}

// ======================= decode kernel ======================================
// 1 CTA per batch row; 256 threads; K/K2 in smem, V in registers, Qe row from L2.
// Target: 113.6 KB smem -> 2 CTAs/SM.
#define DEC_SMEM_FLOATS (2*NN*NPAD + 800 + 100 + 100 + 100 + 128 + 128 + 128 + 256 + 256)
#define DEC_SMEM (DEC_SMEM_FLOATS * 4)

__global__ __launch_bounds__(256, 2) void decode_kernel(const float* __restrict__ capacity,
                                                        const float* __restrict__ demand,
                                                        float* __restrict__ out)
{
    extern __shared__ float sm[];
    float* sK    = sm;                    // [100][132]
    float* sK2   = sK  + NN*NPAD;         // [100][132]
    float* sAttn = sK2 + NN*NPAD;         // [8][100]
    float* sDem  = sAttn + 800;           // 100
    float* sMask = sDem  + 100;           // 100
    float* sMask1= sMask + 100;           // 100
    float* sQ    = sMask1+ 100;           // 128
    float* sQp   = sQ    + 128;           // 128
    float* sWc   = sQp   + 128;           // 128
    float* sPartA= sWc   + 128;           // 256
    float* sPartB= sPartA+ 256;           // 256

    __shared__ float sCap;
    __shared__ int   sIdx;

    int b = blockIdx.x, tid = threadIdx.x;
    int warp = tid >> 5, lane = tid & 31;
    int d = tid & 127, half = tid >> 7, hh = d >> 4;

    // ---- load per-row tiles (K, K2) ----
    {
        const float4* gK  = (const float4*)(g_K  + (size_t)b*NN*HH);
        const float4* gK2 = (const float4*)(g_K2 + (size_t)b*NN*HH);
        for (int j = tid; j < NN*HH/4; j += 256) {
            int n = j >> 5; int c = (j & 31) << 2; int dd = n*NPAD + c;
            *(float4*)&sK [dd] = gK [j];
            *(float4*)&sK2[dd] = gK2[j];
        }
    }
    // ---- V in registers: thread (half,d) holds V[half*50 + i, d], i=0..49 ----
    float vreg[50];
    {
        const float* vg = g_V + (size_t)b*NN*HH + (size_t)(half*50)*HH + d;
        #pragma unroll
        for (int i = 0; i < 50; i++) vreg[i] = vg[i*HH];
    }
    float qv = 0.f;
    if (tid < 128) {
        sQp[tid] = g_qpool[b*HH + tid];
        sWc[tid] = g_Wqf[tid*129 + 128];
        qv = g_Qe[(size_t)b*NN*HH + tid];     // Qe row for idx=0
    }
    if (tid < 100) { sDem[tid] = demand[b*NN + tid]; sMask1[tid] = 0.f; }
    if (tid == 0) sCap = capacity[b];
    __syncthreads();

    const float base_cap = capacity[0];

    // ---- initial mask (update_mask with index=0, mask1=0, go_depot=1) ----
    if (warp == 0) {
        float cap = sCap;
        int cnt = 0; float mv[4];
        #pragma unroll
        for (int k = 0; k < 4; k++) {
            int n = lane + 32*k;
            if (n < 100) {
                float m = (sDem[n] > cap) ? 1.f : 0.f;
                mv[k] = m;
                if (n >= 1 && m == 0.f) cnt++;
            }
        }
        #pragma unroll
        for (int o = 16; o; o >>= 1) cnt += __shfl_xor_sync(0xffffffffu, cnt, o);
        #pragma unroll
        for (int k = 0; k < 4; k++) {
            int n = lane + 32*k;
            if (n >= 1 && n < 100) sMask[n] = mv[k];
        }
        if (lane == 0) sMask[0] = (cnt == 0) ? 0.f : 1.f;
    }
    __syncthreads();

    float logTot = 0.f;  // lane0 of warp0
    int   vis    = 0;
    int   goDepot = 1;

    for (int s = 0; s < STEPS; s++) {
        // ---- A: q row ----
        if (tid < 128) sQ[tid] = qv + sWc[tid]*sCap + sQp[tid];
        __syncthreads();

        // ---- B: scores + softmax fused; warp h owns head h ----
        {
            float sc[4];
            #pragma unroll
            for (int k = 0; k < 4; k++) {
                int n = lane + 32*k;
                float v = -INFINITY;
                if (n < 100) {
                    if (sMask[n] > 0.f) v = NEGV;
                    else {
                        const float4* kp = (const float4*)&sK[n*NPAD + warp*16];
                        const float4* qp = (const float4*)&sQ[warp*16];
                        float4 a0=kp[0], a1=kp[1], a2=kp[2], a3=kp[3];
                        float4 b0=qp[0], b1=qp[1], b2=qp[2], b3=qp[3];
                        v = a0.x*b0.x + a0.y*b0.y + a0.z*b0.z + a0.w*b0.w
                          + a1.x*b1.x + a1.y*b1.y + a1.z*b1.z + a1.w*b1.w
                          + a2.x*b2.x + a2.y*b2.y + a2.z*b2.z + a2.w*b2.w
                          + a3.x*b3.x + a3.y*b3.y + a3.z*b3.z + a3.w*b3.w;
                    }
                }
                sc[k] = v;
            }
            float m = fmaxf(fmaxf(sc[0], sc[1]), fmaxf(sc[2], sc[3]));
            #pragma unroll
            for (int o = 16; o; o >>= 1) m = fmaxf(m, __shfl_xor_sync(0xffffffffu, m, o));
            float e[4]; float sum = 0.f;
            #pragma unroll
            for (int k = 0; k < 4; k++) {
                int n = lane + 32*k;
                if (n < 100) { e[k] = expf(sc[k] - m); sum += e[k]; }
            }
            #pragma unroll
            for (int o = 16; o; o >>= 1) sum += __shfl_xor_sync(0xffffffffu, sum, o);
            #pragma unroll
            for (int k = 0; k < 4; k++) {
                int n = lane + 32*k;
                if (n < 100) sAttn[warp*100 + n] = e[k] / sum;
            }
        }
        __syncthreads();

        // ---- C: glimpse partial g_half[d] = sum attn * V (V in regs) ----
        {
            const float* an = sAttn + hh*100 + half*50;
            float acc = 0.f;
            #pragma unroll
            for (int i = 0; i < 50; i++) acc += an[i] * vreg[i];
            sPartA[tid] = acc;
        }
        __syncthreads();

        // ---- D: u partial = K2'[p] . g  (g recombined inline from sPartA) ----
        if (d < 100) {
            const float* kp = sK2 + d*NPAD + half*64;
            const float* pa = sPartA + half*64;
            float acc = 0.f;
            #pragma unroll
            for (int j = 0; j < 64; j += 4) {
                float4 a = *(const float4*)&kp[j];
                float gx = pa[j]   + pa[j+128];
                float gy = pa[j+1] + pa[j+129];
                float gz = pa[j+2] + pa[j+130];
                float gw = pa[j+3] + pa[j+131];
                acc += a.x*gx + a.y*gy + a.z*gz + a.w*gw;
            }
            sPartB[tid] = acc;
        }
        __syncthreads();

        // ---- E: warp0 — u combine + tanh + argmax + logp + state ----
        if (warp == 0) {
            float uv[4];
            #pragma unroll
            for (int k = 0; k < 4; k++) {
                int n = lane + 32*k;
                if (n < 100) {
                    float t = sPartB[n] + sPartB[n + 128];
                    uv[k] = (sMask[n] > 0.f) ? NEGV : 10.0f * tanhf(t);
                } else uv[k] = -INFINITY;
            }
            float vmax = -INFINITY; int imax = 0;
            #pragma unroll
            for (int k = 0; k < 4; k++) {
                int n = lane + 32*k;
                if (n < 100 && uv[k] > vmax) { vmax = uv[k]; imax = n; }
            }
            #pragma unroll
            for (int o = 16; o; o >>= 1) {
                float ov = __shfl_down_sync(0xffffffffu, vmax, o);
                int   oi = __shfl_down_sync(0xffffffffu, imax, o);
                if (ov > vmax || (ov == vmax && oi < imax)) { vmax = ov; imax = oi; }
            }
            vmax = __shfl_sync(0xffffffffu, vmax, 0);
            imax = __shfl_sync(0xffffffffu, imax, 0);
            float sum = 0.f;
            #pragma unroll
            for (int k = 0; k < 4; k++) {
                int n = lane + 32*k;
                if (n < 100) sum += expf(uv[k] - vmax);
            }
            #pragma unroll
            for (int o = 16; o; o >>= 1) sum += __shfl_xor_sync(0xffffffffu, sum, o);
            if (lane == 0) {
                float logp = -logf(sum);                 // u[argmax]-max == 0
                if (vis < 99) logTot += logp;            // is_done gating (pre-update)
                out[(size_t)b*STEPS + s] = (float)imax;
                float seld = sDem[imax];
                sCap = (imax == 0) ? base_cap : (sCap - seld);
                sIdx = imax;
                if (imax > 0 && sMask1[imax] == 0.f) { sMask1[imax] = 1.f; vis += 1; }
            }
            goDepot = (imax == 0);
        }
        __syncthreads();

        // ---- F: prefetch next Qe row (hides L2 latency under mask update) ----
        if (tid < 128) qv = g_Qe[(size_t)b*NN*HH + (size_t)sIdx*HH + tid];
        if (warp == 0) {
            float cap = sCap;
            int cnt = 0; float mv[4];
            #pragma unroll
            for (int k = 0; k < 4; k++) {
                int n = lane + 32*k;
                if (n < 100) {
                    float m = fmaxf(sMask1[n], (sDem[n] > cap) ? 1.f : 0.f);
                    mv[k] = m;
                    if (n >= 1 && m == 0.f) cnt++;
                }
            }
            #pragma unroll
            for (int o = 16; o; o >>= 1) cnt += __shfl_xor_sync(0xffffffffu, cnt, o);
            #pragma unroll
            for (int k = 0; k < 4; k++) {
                int n = lane + 32*k;
                if (n >= 1 && n < 100) sMask[n] = mv[k];
            }
            if (lane == 0) sMask[0] = (cnt == 0) ? 0.f : (goDepot ? 1.f : 0.f);
        }
        __syncthreads();
    }

    if (tid == 0) out[(size_t)BB*STEPS + b] = logTot;
}

// ======================= launcher ===========================================
extern "C" void kernel_launch(void* const* d_in, const int* in_sizes, int n_in,
                              void* d_out, int out_size)
{
    const float* enc      = (const float*)d_in[0];
    const float* pool     = (const float*)d_in[1];
    const float* capacity = (const float*)d_in[2];
    const float* demand   = (const float*)d_in[3];
    const float* fc_w     = (const float*)d_in[4];
    const float* fc1_w    = (const float*)d_in[5];
    const float* Wq       = (const float*)d_in[6];
    const float* Wk       = (const float*)d_in[7];
    const float* Wv       = (const float*)d_in[8];
    const float* Wo       = (const float*)d_in[9];
    const float* Wk2      = (const float*)d_in[10];
    float* out = (float*)d_out;

    cudaFuncSetAttribute(gemm_kernel,   cudaFuncAttributeMaxDynamicSharedMemorySize, GEMM_SMEM);
    cudaFuncSetAttribute(decode_kernel, cudaFuncAttributeMaxDynamicSharedMemorySize, DEC_SMEM);

    fold_kernel<<<dim3(128, 3), 132>>>(fc_w, fc1_w, Wq, Wo, Wk2);
    gemm_kernel<<<dim3((BB*NN)/GM_TILE, 5), 256, GEMM_SMEM>>>(enc, pool, Wk, Wv);
    decode_kernel<<<BB, 256, DEC_SMEM>>>(capacity, demand, out);
}

// round 3
// speedup vs baseline: 1.8681x; 1.1864x over previous
#include <cuda_runtime.h>
#include <math.h>

// Problem constants
#define BB   1024
#define NN   100
#define HH   128
#define STEPS 128
#define NEGV -1000000000.0f
#define NPAD 132

// -------- device scratch ----
__device__ float g_K [BB*NN*HH];
__device__ float g_V [BB*NN*HH];
__device__ float g_K2[BB*NN*HH];
__device__ float g_Qe[BB*NN*HH];
__device__ float g_qpool[BB*HH];
__device__ float g_Wqf[HH*(HH+1)];
__device__ float g_WfoldT[HH*HH];
__device__ float g_Wpq[HH*HH];
__device__ float g_M [(size_t)BB*NN*8*NN];  // [b][i][h][n]  327 MB
__device__ float g_C2[BB*8*NN];             // [b][h][n]
__device__ float g_C3[BB*8*NN];

// ======================= fold kernel =================================
__global__ void fold_kernel(const float* __restrict__ fc_w,
                            const float* __restrict__ fc1_w,
                            const float* __restrict__ Wq,
                            const float* __restrict__ Wo,
                            const float* __restrict__ Wk2)
{
    int mat = blockIdx.y;
    int r   = blockIdx.x;
    int j   = threadIdx.x;
    if (mat == 0) {
        if (j < 129) {
            float acc = 0.f;
            #pragma unroll 8
            for (int i = 0; i < 128; i++) acc += Wq[r*128 + i] * fc_w[i*129 + j];
            g_Wqf[r*129 + j] = 0.25f * acc;
        }
    } else if (mat == 1) {
        if (j < 128) {
            float acc = 0.f;
            #pragma unroll 8
            for (int i = 0; i < 128; i++) acc += Wk2[i*128 + j] * Wo[i*128 + r];
            g_WfoldT[r*128 + j] = (1.0f / sqrtf(128.0f)) * acc;
        }
    } else {
        if (j < 128) {
            float acc = 0.f;
            #pragma unroll 8
            for (int i = 0; i < 128; i++) acc += Wq[r*128 + i] * fc1_w[i*128 + j];
            g_Wpq[r*128 + j] = 0.25f * acc;
        }
    }
}

// ======================= GEMM: out = A @ W^T ================================
#define GM_TILE 64
#define GEMM_SMEM ((128*132 + GM_TILE*132) * 4)

__global__ __launch_bounds__(256) void gemm_kernel(const float* __restrict__ enc,
                                                   const float* __restrict__ pool,
                                                   const float* __restrict__ Wk,
                                                   const float* __restrict__ Wv)
{
    extern __shared__ float sm[];
    float* sW = sm;
    float* sA = sm + 128*132;

    int slice = blockIdx.y;
    const float* A; const float* W; float* O; int rows; int ldw = 128;
    if      (slice == 0) { A = enc;  W = Wk;       O = g_K;     rows = BB*NN; }
    else if (slice == 1) { A = enc;  W = Wv;       O = g_V;     rows = BB*NN; }
    else if (slice == 2) { A = enc;  W = g_WfoldT; O = g_K2;    rows = BB*NN; }
    else if (slice == 3) { A = enc;  W = g_Wqf;    O = g_Qe;    rows = BB*NN; ldw = 129; }
    else                 { A = pool; W = g_Wpq;    O = g_qpool; rows = BB;    }

    int row0 = blockIdx.x * GM_TILE;
    if (row0 >= rows) return;
    int tid = threadIdx.x;

    for (int i = tid; i < 128*128; i += 256) {
        int c = i >> 7, m = i & 127;
        sW[m*132 + c] = W[c*ldw + m];
    }
    for (int i = tid; i < GM_TILE*128; i += 256) {
        int r = i >> 7, k = i & 127;
        sA[r*132 + k] = A[(row0 + r)*128 + k];
    }
    __syncthreads();

    int warp = tid >> 5, lane = tid & 31;
    int r0 = warp * 8, c0 = lane * 4;
    float acc[8][4];
    #pragma unroll
    for (int i = 0; i < 8; i++) { acc[i][0]=0; acc[i][1]=0; acc[i][2]=0; acc[i][3]=0; }

    #pragma unroll 4
    for (int k = 0; k < 128; k++) {
        float4 w4 = *(const float4*)&sW[k*132 + c0];
        #pragma unroll
        for (int i = 0; i < 8; i++) {
            float a = sA[(r0 + i)*132 + k];
            acc[i][0] += a * w4.x;
            acc[i][1] += a * w4.y;
            acc[i][2] += a * w4.z;
            acc[i][3] += a * w4.w;
        }
    }
    #pragma unroll
    for (int i = 0; i < 8; i++) {
        float4 v; v.x = acc[i][0]; v.y = acc[i][1]; v.z = acc[i][2]; v.w = acc[i][3];
        *(float4*)&O[(size_t)(row0 + r0 + i)*128 + c0] = v;
    }
}

// ======================= score precompute ===================================
// Per row b: M[i,h,n] = dot16(Qe[i,h], K[n,h]); c2 = dot16(K,Wc); c3 = dot16(K,qpool)
#define SP_SMEM (NN*128*4)
__global__ __launch_bounds__(256, 2) void score_pre_kernel()
{
    extern __shared__ float sQe[];
    int b = blockIdx.x, tid = threadIdx.x;
    int h = tid >> 5, lane = tid & 31;

    const float* qe = g_Qe + (size_t)b*NN*HH;
    for (int j = tid; j < NN*HH/4; j += 256)
        *(float4*)&sQe[j*4] = ((const float4*)qe)[j];

    float kr[4][16];
    float wc[16], qp[16];
    #pragma unroll
    for (int j = 0; j < 16; j++) {
        wc[j] = g_Wqf[(h*16+j)*129 + 128];
        qp[j] = g_qpool[b*HH + h*16 + j];
    }
    #pragma unroll
    for (int k = 0; k < 4; k++) {
        int n = lane + 32*k;
        if (n < NN) {
            const float* kp = g_K + (size_t)b*NN*HH + (size_t)n*HH + h*16;
            #pragma unroll
            for (int j = 0; j < 16; j += 4) {
                float4 v = *(const float4*)&kp[j];
                kr[k][j]=v.x; kr[k][j+1]=v.y; kr[k][j+2]=v.z; kr[k][j+3]=v.w;
            }
        }
    }
    #pragma unroll
    for (int k = 0; k < 4; k++) {
        int n = lane + 32*k;
        if (n < NN) {
            float a2 = 0.f, a3 = 0.f;
            #pragma unroll
            for (int j = 0; j < 16; j++) { a2 += kr[k][j]*wc[j]; a3 += kr[k][j]*qp[j]; }
            g_C2[((size_t)b*8 + h)*NN + n] = a2;
            g_C3[((size_t)b*8 + h)*NN + n] = a3;
        }
    }
    __syncthreads();

    float* Mb = g_M + (size_t)b*NN*8*NN;
    for (int i = 0; i < NN; i++) {
        float q[16];
        #pragma unroll
        for (int j = 0; j < 16; j += 4) {
            float4 v = *(const float4*)&sQe[i*128 + h*16 + j];
            q[j]=v.x; q[j+1]=v.y; q[j+2]=v.z; q[j+3]=v.w;
        }
        #pragma unroll
        for (int k = 0; k < 4; k++) {
            int n = lane + 32*k;
            if (n < NN) {
                float acc = 0.f;
                #pragma unroll
                for (int j = 0; j < 16; j++) acc += kr[k][j]*q[j];
                Mb[((size_t)i*8 + h)*NN + n] = acc;
            }
        }
    }
}

// ======================= decode kernel ======================================
// 1 CTA/row; 256 threads; K2 in smem, V in regs, scores via M + cap*c2 + c3.
// smem ~64.2 KB -> 3 CTAs/SM.
#define DEC_SMEM_FLOATS (NN*NPAD + 800 + 800 + 800 + 100 + 100 + 100 + 256 + 256 + 16)
#define DEC_SMEM (DEC_SMEM_FLOATS * 4)

__global__ __launch_bounds__(256, 3) void decode_kernel(const float* __restrict__ capacity,
                                                        const float* __restrict__ demand,
                                                        float* __restrict__ out)
{
    extern __shared__ float sm[];
    float* sK2   = sm;                    // [100][132]
    float* sAttn = sK2   + NN*NPAD;       // 800
    float* sC2   = sAttn + 800;           // 800
    float* sC3   = sC2   + 800;           // 800
    float* sDem  = sC3   + 800;           // 100
    float* sMask = sDem  + 100;           // 100
    float* sMask1= sMask + 100;           // 100
    float* sPartA= sMask1+ 100;           // 256
    float* sPartB= sPartA+ 256;           // 256

    __shared__ float sCap;
    __shared__ int   sIdx;

    int b = blockIdx.x, tid = threadIdx.x;
    int warp = tid >> 5, lane = tid & 31;
    int d = tid & 127, half = tid >> 7, hh = d >> 4;

    // ---- loads ----
    {
        const float4* gK2 = (const float4*)(g_K2 + (size_t)b*NN*HH);
        for (int j = tid; j < NN*HH/4; j += 256) {
            int n = j >> 5; int c = (j & 31) << 2;
            *(float4*)&sK2[n*NPAD + c] = gK2[j];
        }
    }
    float vreg[50];
    {
        const float* vg = g_V + (size_t)b*NN*HH + (size_t)(half*50)*HH + d;
        #pragma unroll
        for (int i = 0; i < 50; i++) vreg[i] = vg[i*HH];
    }
    for (int j = tid; j < 800; j += 256) {
        sC2[j] = g_C2[(size_t)b*800 + j];
        sC3[j] = g_C3[(size_t)b*800 + j];
    }
    if (tid < 100) { sDem[tid] = demand[b*NN + tid]; sMask1[tid] = 0.f; }
    if (tid == 0) { sCap = capacity[b]; sIdx = 0; }

    // prefetch M row for i=0
    float mrow[4];
    {
        const float* mp = g_M + ((size_t)b*NN*8 + warp)*NN;
        #pragma unroll
        for (int k = 0; k < 4; k++) { int n = lane + 32*k; mrow[k] = (n < NN) ? mp[n] : 0.f; }
    }
    __syncthreads();

    const float base_cap = capacity[0];

    // ---- initial mask (index=0, mask1=0, go_depot=1) ----
    if (warp == 0) {
        float cap = sCap; int cnt = 0;
        #pragma unroll
        for (int k = 0; k < 4; k++) {
            int n = lane + 32*k;
            if (n >= 1 && n < 100) {
                float m = (sDem[n] > cap) ? 1.f : 0.f;
                sMask[n] = m;
                if (m == 0.f) cnt++;
            }
        }
        #pragma unroll
        for (int o = 16; o; o >>= 1) cnt += __shfl_xor_sync(0xffffffffu, cnt, o);
        if (lane == 0) sMask[0] = (cnt == 0) ? 0.f : 1.f;
    }
    __syncthreads();

    float logTot = 0.f;
    int   vis    = 0;

    for (int s = 0; s < STEPS; s++) {
        // ---- B: scores = M[idx] + cap*c2 + c3; softmax; warp h = head h ----
        {
            float cap = sCap;
            float sc[4];
            #pragma unroll
            for (int k = 0; k < 4; k++) {
                int n = lane + 32*k;
                float v = -INFINITY;
                if (n < 100) {
                    if (sMask[n] > 0.f) v = NEGV;
                    else v = mrow[k] + cap*sC2[warp*100 + n] + sC3[warp*100 + n];
                }
                sc[k] = v;
            }
            float m = fmaxf(fmaxf(sc[0], sc[1]), fmaxf(sc[2], sc[3]));
            #pragma unroll
            for (int o = 16; o; o >>= 1) m = fmaxf(m, __shfl_xor_sync(0xffffffffu, m, o));
            float e[4]; float sum = 0.f;
            #pragma unroll
            for (int k = 0; k < 4; k++) {
                int n = lane + 32*k;
                if (n < 100) { e[k] = expf(sc[k] - m); sum += e[k]; }
            }
            #pragma unroll
            for (int o = 16; o; o >>= 1) sum += __shfl_xor_sync(0xffffffffu, sum, o);
            #pragma unroll
            for (int k = 0; k < 4; k++) {
                int n = lane + 32*k;
                if (n < 100) sAttn[warp*100 + n] = e[k] / sum;
            }
        }
        __syncthreads();

        // ---- C: glimpse partials (V in regs) ----
        {
            const float* an = sAttn + hh*100 + half*50;
            float acc = 0.f;
            #pragma unroll
            for (int i = 0; i < 50; i++) acc += an[i] * vreg[i];
            sPartA[tid] = acc;
        }
        __syncthreads();

        // ---- D: u partial = K2'[d] . g ----
        if (d < 100) {
            const float* kp = sK2 + d*NPAD + half*64;
            const float* pa = sPartA + half*64;
            float acc = 0.f;
            #pragma unroll
            for (int j = 0; j < 64; j += 4) {
                float4 a = *(const float4*)&kp[j];
                float gx = pa[j]   + pa[j+128];
                float gy = pa[j+1] + pa[j+129];
                float gz = pa[j+2] + pa[j+130];
                float gw = pa[j+3] + pa[j+131];
                acc += a.x*gx + a.y*gy + a.z*gz + a.w*gw;
            }
            sPartB[tid] = acc;
        }
        __syncthreads();

        // ---- E: warp0 — u, argmax, logp, state + mask update (fused) ----
        if (warp == 0) {
            float uv[4];
            #pragma unroll
            for (int k = 0; k < 4; k++) {
                int n = lane + 32*k;
                if (n < 100) {
                    float t = sPartB[n] + sPartB[n + 128];
                    uv[k] = (sMask[n] > 0.f) ? NEGV : 10.0f * tanhf(t);
                } else uv[k] = -INFINITY;
            }
            float vmax = -INFINITY; int imax = 0;
            #pragma unroll
            for (int k = 0; k < 4; k++) {
                int n = lane + 32*k;
                if (n < 100 && uv[k] > vmax) { vmax = uv[k]; imax = n; }
            }
            #pragma unroll
            for (int o = 16; o; o >>= 1) {
                float ov = __shfl_down_sync(0xffffffffu, vmax, o);
                int   oi = __shfl_down_sync(0xffffffffu, imax, o);
                if (ov > vmax || (ov == vmax && oi < imax)) { vmax = ov; imax = oi; }
            }
            vmax = __shfl_sync(0xffffffffu, vmax, 0);
            imax = __shfl_sync(0xffffffffu, imax, 0);
            float sum = 0.f;
            #pragma unroll
            for (int k = 0; k < 4; k++) {
                int n = lane + 32*k;
                if (n < 100) sum += expf(uv[k] - vmax);
            }
            #pragma unroll
            for (int o = 16; o; o >>= 1) sum += __shfl_xor_sync(0xffffffffu, sum, o);

            float capNew = 0.f;
            if (lane == 0) {
                float logp = -logf(sum);
                if (vis < 99) logTot += logp;
                out[(size_t)b*STEPS + s] = (float)imax;
                float seld = sDem[imax];
                capNew = (imax == 0) ? base_cap : (sCap - seld);
                sCap = capNew; sIdx = imax;
                if (imax > 0 && sMask1[imax] == 0.f) { sMask1[imax] = 1.f; vis += 1; }
            }
            __syncwarp();
            capNew = __shfl_sync(0xffffffffu, capNew, 0);
            int goDepot = (imax == 0);

            int cnt = 0; float mv[4];
            #pragma unroll
            for (int k = 0; k < 4; k++) {
                int n = lane + 32*k;
                mv[k] = 0.f;
                if (n >= 1 && n < 100) {
                    float m = fmaxf(sMask1[n], (sDem[n] > capNew) ? 1.f : 0.f);
                    mv[k] = m;
                    if (m == 0.f) cnt++;
                }
            }
            #pragma unroll
            for (int o = 16; o; o >>= 1) cnt += __shfl_xor_sync(0xffffffffu, cnt, o);
            #pragma unroll
            for (int k = 0; k < 4; k++) {
                int n = lane + 32*k;
                if (n >= 1 && n < 100) sMask[n] = mv[k];
            }
            if (lane == 0) sMask[0] = (cnt == 0) ? 0.f : (goDepot ? 1.f : 0.f);
        }
        __syncthreads();

        // ---- prefetch next M row (uses sIdx; overlaps into next B) ----
        {
            int idx = sIdx;
            const float* mp = g_M + (((size_t)b*NN + idx)*8 + warp)*NN;
            #pragma unroll
            for (int k = 0; k < 4; k++) { int n = lane + 32*k; if (n < NN) mrow[k] = mp[n]; }
        }
    }

    if (tid == 0) out[(size_t)BB*STEPS + b] = logTot;
}

// ======================= launcher ===========================================
extern "C" void kernel_launch(void* const* d_in, const int* in_sizes, int n_in,
                              void* d_out, int out_size)
{
    const float* enc      = (const float*)d_in[0];
    const float* pool     = (const float*)d_in[1];
    const float* capacity = (const float*)d_in[2];
    const float* demand   = (const float*)d_in[3];
    const float* fc_w     = (const float*)d_in[4];
    const float* fc1_w    = (const float*)d_in[5];
    const float* Wq       = (const float*)d_in[6];
    const float* Wk       = (const float*)d_in[7];
    const float* Wv       = (const float*)d_in[8];
    const float* Wo       = (const float*)d_in[9];
    const float* Wk2      = (const float*)d_in[10];
    float* out = (float*)d_out;

    cudaFuncSetAttribute(gemm_kernel,      cudaFuncAttributeMaxDynamicSharedMemorySize, GEMM_SMEM);
    cudaFuncSetAttribute(score_pre_kernel, cudaFuncAttributeMaxDynamicSharedMemorySize, SP_SMEM);
    cudaFuncSetAttribute(decode_kernel,    cudaFuncAttributeMaxDynamicSharedMemorySize, DEC_SMEM);

    fold_kernel<<<dim3(128, 3), 132>>>(fc_w, fc1_w, Wq, Wo, Wk2);
    gemm_kernel<<<dim3((BB*NN)/GM_TILE, 5), 256, GEMM_SMEM>>>(enc, pool, Wk, Wv);
    score_pre_kernel<<<BB, 256, SP_SMEM>>>();
    decode_kernel<<<BB, 256, DEC_SMEM>>>(capacity, demand, out);
}

// round 4
// speedup vs baseline: 2.0319x; 1.0877x over previous
#include <cuda_runtime.h>
#include <math.h>

// Problem constants
#define BB   1024
#define NN   100
#define HH   128
#define STEPS 128
#define NEGV -1000000000.0f
#define NPAD 132

// packed f32x2 helpers (Blackwell FFMA2 — bit-identical per-lane IEEE fma)
#define PK2(d, x, y)  asm("mov.b64 %0, {%1, %2};" : "=l"(d) : "f"(x), "f"(y))
#define UPK2(x, y, d) asm("mov.b64 {%0, %1}, %2;" : "=f"(x), "=f"(y) : "l"(d))
#define FMA2(d, a, b) asm("fma.rn.f32x2 %0, %1, %2, %0;" : "+l"(d) : "l"(a), "l"(b))

// -------- device scratch ----
__device__ float g_K [BB*NN*HH];
__device__ float g_V [BB*NN*HH];
__device__ float g_K2[BB*NN*HH];
__device__ float g_Qe[BB*NN*HH];
__device__ float g_qpool[BB*HH];
__device__ float g_Wqf[HH*(HH+1)];
__device__ float g_WfoldT[HH*HH];
__device__ float g_Wpq[HH*HH];
__device__ float g_M [(size_t)BB*NN*8*NN];  // [b][i][h][n]
__device__ float g_C2[BB*8*NN];             // [b][h][n]
__device__ float g_C3[BB*8*NN];

// ======================= fold kernel =================================
__global__ void fold_kernel(const float* __restrict__ fc_w,
                            const float* __restrict__ fc1_w,
                            const float* __restrict__ Wq,
                            const float* __restrict__ Wo,
                            const float* __restrict__ Wk2)
{
    int mat = blockIdx.y;
    int r   = blockIdx.x;
    int j   = threadIdx.x;
    if (mat == 0) {
        if (j < 129) {
            float acc = 0.f;
            #pragma unroll 8
            for (int i = 0; i < 128; i++) acc += Wq[r*128 + i] * fc_w[i*129 + j];
            g_Wqf[r*129 + j] = 0.25f * acc;
        }
    } else if (mat == 1) {
        if (j < 128) {
            float acc = 0.f;
            #pragma unroll 8
            for (int i = 0; i < 128; i++) acc += Wk2[i*128 + j] * Wo[i*128 + r];
            g_WfoldT[r*128 + j] = (1.0f / sqrtf(128.0f)) * acc;
        }
    } else {
        if (j < 128) {
            float acc = 0.f;
            #pragma unroll 8
            for (int i = 0; i < 128; i++) acc += Wq[r*128 + i] * fc1_w[i*128 + j];
            g_Wpq[r*128 + j] = 0.25f * acc;
        }
    }
}

// ======================= GEMM: out = A @ W^T (FFMA2) ========================
#define GM_TILE 64
#define GEMM_SMEM ((128*132 + GM_TILE*132) * 4)

__global__ __launch_bounds__(256) void gemm_kernel(const float* __restrict__ enc,
                                                   const float* __restrict__ pool,
                                                   const float* __restrict__ Wk,
                                                   const float* __restrict__ Wv)
{
    extern __shared__ float sm[];
    float* sW = sm;                 // [128][132]  sW[k*132 + c] = W[c][k]
    float* sA = sm + 128*132;       // [64][132]

    int slice = blockIdx.y;
    const float* A; const float* W; float* O; int rows; int ldw = 128;
    if      (slice == 0) { A = enc;  W = Wk;       O = g_K;     rows = BB*NN; }
    else if (slice == 1) { A = enc;  W = Wv;       O = g_V;     rows = BB*NN; }
    else if (slice == 2) { A = enc;  W = g_WfoldT; O = g_K2;    rows = BB*NN; }
    else if (slice == 3) { A = enc;  W = g_Wqf;    O = g_Qe;    rows = BB*NN; ldw = 129; }
    else                 { A = pool; W = g_Wpq;    O = g_qpool; rows = BB;    }

    int row0 = blockIdx.x * GM_TILE;
    if (row0 >= rows) return;
    int tid = threadIdx.x;

    for (int i = tid; i < 128*128; i += 256) {
        int c = i >> 7, m = i & 127;
        sW[m*132 + c] = W[c*ldw + m];
    }
    for (int i = tid; i < GM_TILE*128; i += 256) {
        int r = i >> 7, k = i & 127;
        sA[r*132 + k] = A[(row0 + r)*128 + k];
    }
    __syncthreads();

    int warp = tid >> 5, lane = tid & 31;
    int r0 = warp * 8, c0 = lane * 4;

    // accp[c][t] packs (acc[row 2t][c], acc[row 2t+1][c]) — per-element chains
    // identical to scalar FFMA accumulation over k (bit-exact).
    unsigned long long accp[4][4];
    #pragma unroll
    for (int c = 0; c < 4; c++)
        #pragma unroll
        for (int t = 0; t < 4; t++) PK2(accp[c][t], 0.f, 0.f);

    #pragma unroll 4
    for (int k = 0; k < 128; k++) {
        float4 w4 = *(const float4*)&sW[k*132 + c0];
        unsigned long long wd[4];
        PK2(wd[0], w4.x, w4.x); PK2(wd[1], w4.y, w4.y);
        PK2(wd[2], w4.z, w4.z); PK2(wd[3], w4.w, w4.w);
        unsigned long long ap[4];
        #pragma unroll
        for (int t = 0; t < 4; t++) {
            float a0 = sA[(r0 + 2*t    )*132 + k];
            float a1 = sA[(r0 + 2*t + 1)*132 + k];
            PK2(ap[t], a0, a1);
        }
        #pragma unroll
        for (int c = 0; c < 4; c++)
            #pragma unroll
            for (int t = 0; t < 4; t++) FMA2(accp[c][t], ap[t], wd[c]);
    }

    #pragma unroll
    for (int t = 0; t < 4; t++) {
        float4 v0, v1;
        UPK2(v0.x, v1.x, accp[0][t]);
        UPK2(v0.y, v1.y, accp[1][t]);
        UPK2(v0.z, v1.z, accp[2][t]);
        UPK2(v0.w, v1.w, accp[3][t]);
        *(float4*)&O[(size_t)(row0 + r0 + 2*t    )*128 + c0] = v0;
        *(float4*)&O[(size_t)(row0 + r0 + 2*t + 1)*128 + c0] = v1;
    }
}

// ======================= score precompute ===================================
#define SP_SMEM (NN*128*4)
__global__ __launch_bounds__(256, 2) void score_pre_kernel()
{
    extern __shared__ float sQe[];
    int b = blockIdx.x, tid = threadIdx.x;
    int h = tid >> 5, lane = tid & 31;

    const float* qe = g_Qe + (size_t)b*NN*HH;
    for (int j = tid; j < NN*HH/4; j += 256)
        *(float4*)&sQe[j*4] = ((const float4*)qe)[j];

    float kr[4][16];
    float wc[16], qp[16];
    #pragma unroll
    for (int j = 0; j < 16; j++) {
        wc[j] = g_Wqf[(h*16+j)*129 + 128];
        qp[j] = g_qpool[b*HH + h*16 + j];
    }
    #pragma unroll
    for (int k = 0; k < 4; k++) {
        int n = lane + 32*k;
        if (n < NN) {
            const float* kp = g_K + (size_t)b*NN*HH + (size_t)n*HH + h*16;
            #pragma unroll
            for (int j = 0; j < 16; j += 4) {
                float4 v = *(const float4*)&kp[j];
                kr[k][j]=v.x; kr[k][j+1]=v.y; kr[k][j+2]=v.z; kr[k][j+3]=v.w;
            }
        }
    }
    #pragma unroll
    for (int k = 0; k < 4; k++) {
        int n = lane + 32*k;
        if (n < NN) {
            float a2 = 0.f, a3 = 0.f;
            #pragma unroll
            for (int j = 0; j < 16; j++) { a2 += kr[k][j]*wc[j]; a3 += kr[k][j]*qp[j]; }
            g_C2[((size_t)b*8 + h)*NN + n] = a2;
            g_C3[((size_t)b*8 + h)*NN + n] = a3;
        }
    }
    __syncthreads();

    float* Mb = g_M + (size_t)b*NN*8*NN;
    for (int i = 0; i < NN; i++) {
        float q[16];
        #pragma unroll
        for (int j = 0; j < 16; j += 4) {
            float4 v = *(const float4*)&sQe[i*128 + h*16 + j];
            q[j]=v.x; q[j+1]=v.y; q[j+2]=v.z; q[j+3]=v.w;
        }
        #pragma unroll
        for (int k = 0; k < 4; k++) {
            int n = lane + 32*k;
            if (n < NN) {
                float acc = 0.f;
                #pragma unroll
                for (int j = 0; j < 16; j++) acc += kr[k][j]*q[j];
                Mb[((size_t)i*8 + h)*NN + n] = acc;
            }
        }
    }
}

// ======================= decode kernel ======================================
// smem floats: sK2 13200 + sAttn 832 + sC2 800 + sC3 800 + sDem 100 + sMask 100
//            + sMask1 100 + sPartA 256 + sG 128 + sU 104 = 16420 (~65.7 KB) -> 3 CTAs/SM
#define DEC_SMEM_FLOATS (NN*NPAD + 832 + 800 + 800 + 100 + 100 + 100 + 256 + 128 + 104)
#define DEC_SMEM (DEC_SMEM_FLOATS * 4)
#define APAD 104

__global__ __launch_bounds__(256, 3) void decode_kernel(const float* __restrict__ capacity,
                                                        const float* __restrict__ demand,
                                                        float* __restrict__ out)
{
    extern __shared__ float sm[];
    float* sK2   = sm;                    // [100][132]
    float* sAttn = sK2   + NN*NPAD;       // [8][104]  (halves at +0 / +52)
    float* sC2   = sAttn + 832;
    float* sC3   = sC2   + 800;
    float* sDem  = sC3   + 800;
    float* sMask = sDem  + 100;
    float* sMask1= sMask + 100;
    float* sPartA= sMask1+ 100;           // 256
    float* sG    = sPartA+ 256;           // 128
    float* sU    = sG    + 128;           // 104

    __shared__ float sCap;
    __shared__ int   sIdx;

    int b = blockIdx.x, tid = threadIdx.x;
    int warp = tid >> 5, lane = tid & 31;
    int d = tid & 127, half = tid >> 7, hh = d >> 4;

    // ---- loads ----
    {
        const float4* gK2 = (const float4*)(g_K2 + (size_t)b*NN*HH);
        for (int j = tid; j < NN*HH/4; j += 256) {
            int n = j >> 5; int c = (j & 31) << 2;
            *(float4*)&sK2[n*NPAD + c] = gK2[j];
        }
    }
    float vreg[50];
    {
        const float* vg = g_V + (size_t)b*NN*HH + (size_t)(half*50)*HH + d;
        #pragma unroll
        for (int i = 0; i < 50; i++) vreg[i] = vg[i*HH];
    }
    for (int j = tid; j < 800; j += 256) {
        sC2[j] = g_C2[(size_t)b*800 + j];
        sC3[j] = g_C3[(size_t)b*800 + j];
    }
    if (tid < 100) { sDem[tid] = demand[b*NN + tid]; sMask1[tid] = 0.f; }
    if (tid == 0) { sCap = capacity[b]; sIdx = 0; }

    float mrow[4];
    {
        const float* mp = g_M + ((size_t)b*NN*8 + warp)*NN;
        #pragma unroll
        for (int k = 0; k < 4; k++) { int n = lane + 32*k; mrow[k] = (n < NN) ? mp[n] : 0.f; }
    }
    __syncthreads();

    const float base_cap = capacity[0];

    // ---- initial mask (index=0, mask1=0, go_depot=1) ----
    if (warp == 0) {
        float cap = sCap; int cnt = 0;
        #pragma unroll
        for (int k = 0; k < 4; k++) {
            int n = lane + 32*k;
            if (n >= 1 && n < 100) {
                float m = (sDem[n] > cap) ? 1.f : 0.f;
                sMask[n] = m;
                if (m == 0.f) cnt++;
            }
        }
        #pragma unroll
        for (int o = 16; o; o >>= 1) cnt += __shfl_xor_sync(0xffffffffu, cnt, o);
        if (lane == 0) sMask[0] = (cnt == 0) ? 0.f : 1.f;
    }
    __syncthreads();

    float logTot = 0.f;
    int   vis    = 0;

    for (int s = 0; s < STEPS; s++) {
        // ---- B: scores = M[idx] + cap*c2 + c3; softmax; warp h = head h ----
        {
            float cap = sCap;
            float sc[4];
            #pragma unroll
            for (int k = 0; k < 4; k++) {
                int n = lane + 32*k;
                float v = -INFINITY;
                if (n < 100) {
                    if (sMask[n] > 0.f) v = NEGV;
                    else v = mrow[k] + cap*sC2[warp*100 + n] + sC3[warp*100 + n];
                }
                sc[k] = v;
            }
            float m = fmaxf(fmaxf(sc[0], sc[1]), fmaxf(sc[2], sc[3]));
            #pragma unroll
            for (int o = 16; o; o >>= 1) m = fmaxf(m, __shfl_xor_sync(0xffffffffu, m, o));
            float e[4]; float sum = 0.f;
            #pragma unroll
            for (int k = 0; k < 4; k++) {
                int n = lane + 32*k;
                if (n < 100) { e[k] = expf(sc[k] - m); sum += e[k]; }
            }
            #pragma unroll
            for (int o = 16; o; o >>= 1) sum += __shfl_xor_sync(0xffffffffu, sum, o);
            #pragma unroll
            for (int k = 0; k < 4; k++) {
                int n = lane + 32*k;
                if (n < 100) {
                    int off = warp*APAD + n + ((n >= 50) ? 2 : 0);
                    sAttn[off] = e[k] / sum;
                }
            }
        }
        __syncthreads();

        // ---- C: glimpse partials (V in regs, float4 attn reads) ----
        {
            const float* an = sAttn + hh*APAD + half*52;
            float acc = 0.f;
            #pragma unroll
            for (int i = 0; i < 48; i += 4) {
                float4 a4 = *(const float4*)&an[i];
                acc = fmaf(a4.x, vreg[i],   acc);
                acc = fmaf(a4.y, vreg[i+1], acc);
                acc = fmaf(a4.z, vreg[i+2], acc);
                acc = fmaf(a4.w, vreg[i+3], acc);
            }
            acc = fmaf(an[48], vreg[48], acc);
            acc = fmaf(an[49], vreg[49], acc);
            sPartA[tid] = acc;
        }
        __syncthreads();

        // ---- warps 0-3 only: g-combine -> u -> argmax/state ----
        if (tid < 128) {
            sG[tid] = sPartA[tid] + sPartA[tid + 128];
            asm volatile("bar.sync 1, 128;" ::: "memory");

            if (tid < 100) {
                const float* kp = sK2 + tid*NPAD;
                float acc0 = 0.f, acc1 = 0.f;
                #pragma unroll
                for (int j = 0; j < 64; j += 4) {
                    float4 a = *(const float4*)&kp[j];
                    float4 g = *(const float4*)&sG[j];
                    acc0 = fmaf(a.x, g.x, acc0);
                    acc0 = fmaf(a.y, g.y, acc0);
                    acc0 = fmaf(a.z, g.z, acc0);
                    acc0 = fmaf(a.w, g.w, acc0);
                }
                #pragma unroll
                for (int j = 64; j < 128; j += 4) {
                    float4 a = *(const float4*)&kp[j];
                    float4 g = *(const float4*)&sG[j];
                    acc1 = fmaf(a.x, g.x, acc1);
                    acc1 = fmaf(a.y, g.y, acc1);
                    acc1 = fmaf(a.z, g.z, acc1);
                    acc1 = fmaf(a.w, g.w, acc1);
                }
                float t = acc0 + acc1;
                sU[tid] = (sMask[tid] > 0.f) ? NEGV : 10.0f * tanhf(t);
            }
            asm volatile("bar.sync 1, 128;" ::: "memory");

            // ---- E: warp0 — argmax, logp, state + mask update ----
            if (warp == 0) {
                float uv[4];
                #pragma unroll
                for (int k = 0; k < 4; k++) {
                    int n = lane + 32*k;
                    uv[k] = (n < 100) ? sU[n] : -INFINITY;
                }
                float vmax = -INFINITY; int imax = 0;
                #pragma unroll
                for (int k = 0; k < 4; k++) {
                    int n = lane + 32*k;
                    if (n < 100 && uv[k] > vmax) { vmax = uv[k]; imax = n; }
                }
                #pragma unroll
                for (int o = 16; o; o >>= 1) {
                    float ov = __shfl_down_sync(0xffffffffu, vmax, o);
                    int   oi = __shfl_down_sync(0xffffffffu, imax, o);
                    if (ov > vmax || (ov == vmax && oi < imax)) { vmax = ov; imax = oi; }
                }
                vmax = __shfl_sync(0xffffffffu, vmax, 0);
                imax = __shfl_sync(0xffffffffu, imax, 0);
                float sum = 0.f;
                #pragma unroll
                for (int k = 0; k < 4; k++) {
                    int n = lane + 32*k;
                    if (n < 100) sum += expf(uv[k] - vmax);
                }
                #pragma unroll
                for (int o = 16; o; o >>= 1) sum += __shfl_xor_sync(0xffffffffu, sum, o);

                float capNew = 0.f;
                if (lane == 0) {
                    float logp = -logf(sum);
                    if (vis < 99) logTot += logp;
                    out[(size_t)b*STEPS + s] = (float)imax;
                    float seld = sDem[imax];
                    capNew = (imax == 0) ? base_cap : (sCap - seld);
                    sCap = capNew; sIdx = imax;
                    if (imax > 0 && sMask1[imax] == 0.f) { sMask1[imax] = 1.f; vis += 1; }
                }
                __syncwarp();
                capNew = __shfl_sync(0xffffffffu, capNew, 0);
                int goDepot = (imax == 0);

                int cnt = 0; float mv[4];
                #pragma unroll
                for (int k = 0; k < 4; k++) {
                    int n = lane + 32*k;
                    mv[k] = 0.f;
                    if (n >= 1 && n < 100) {
                        float m = fmaxf(sMask1[n], (sDem[n] > capNew) ? 1.f : 0.f);
                        mv[k] = m;
                        if (m == 0.f) cnt++;
                    }
                }
                #pragma unroll
                for (int o = 16; o; o >>= 1) cnt += __shfl_xor_sync(0xffffffffu, cnt, o);
                #pragma unroll
                for (int k = 0; k < 4; k++) {
                    int n = lane + 32*k;
                    if (n >= 1 && n < 100) sMask[n] = mv[k];
                }
                if (lane == 0) sMask[0] = (cnt == 0) ? 0.f : (goDepot ? 1.f : 0.f);
            }
        }
        __syncthreads();

        // ---- prefetch next M row ----
        {
            int idx = sIdx;
            const float* mp = g_M + (((size_t)b*NN + idx)*8 + warp)*NN;
            #pragma unroll
            for (int k = 0; k < 4; k++) { int n = lane + 32*k; if (n < NN) mrow[k] = mp[n]; }
        }
    }

    if (tid == 0) out[(size_t)BB*STEPS + b] = logTot;
}

// ======================= launcher ===========================================
extern "C" void kernel_launch(void* const* d_in, const int* in_sizes, int n_in,
                              void* d_out, int out_size)
{
    const float* enc      = (const float*)d_in[0];
    const float* pool     = (const float*)d_in[1];
    const float* capacity = (const float*)d_in[2];
    const float* demand   = (const float*)d_in[3];
    const float* fc_w     = (const float*)d_in[4];
    const float* fc1_w    = (const float*)d_in[5];
    const float* Wq       = (const float*)d_in[6];
    const float* Wk       = (const float*)d_in[7];
    const float* Wv       = (const float*)d_in[8];
    const float* Wo       = (const float*)d_in[9];
    const float* Wk2      = (const float*)d_in[10];
    float* out = (float*)d_out;

    cudaFuncSetAttribute(gemm_kernel,      cudaFuncAttributeMaxDynamicSharedMemorySize, GEMM_SMEM);
    cudaFuncSetAttribute(score_pre_kernel, cudaFuncAttributeMaxDynamicSharedMemorySize, SP_SMEM);
    cudaFuncSetAttribute(decode_kernel,    cudaFuncAttributeMaxDynamicSharedMemorySize, DEC_SMEM);

    fold_kernel<<<dim3(128, 3), 132>>>(fc_w, fc1_w, Wq, Wo, Wk2);
    gemm_kernel<<<dim3((BB*NN)/GM_TILE, 5), 256, GEMM_SMEM>>>(enc, pool, Wk, Wv);
    score_pre_kernel<<<BB, 256, SP_SMEM>>>();
    decode_kernel<<<BB, 256, DEC_SMEM>>>(capacity, demand, out);
}

// round 6
// speedup vs baseline: 2.5038x; 1.2322x over previous
#include <cuda_runtime.h>
#include <math.h>

// Problem constants
#define BB   1024
#define NN   100
#define HH   128
#define STEPS 128
#define NEGV -1000000000.0f
#define NPAD 132

// packed f32x2 helpers (Blackwell FFMA2 — bit-identical per-lane IEEE fma)
#define PK2(d, x, y)  asm("mov.b64 %0, {%1, %2};" : "=l"(d) : "f"(x), "f"(y))
#define UPK2(x, y, d) asm("mov.b64 {%0, %1}, %2;" : "=f"(x), "=f"(y) : "l"(d))
#define FMA2(d, a, b) asm("fma.rn.f32x2 %0, %1, %2, %0;" : "+l"(d) : "l"(a), "l"(b))

// -------- device scratch ----
__device__ float g_K [BB*NN*HH];
__device__ float g_V [BB*NN*HH];
__device__ float g_K2[BB*NN*HH];
__device__ float g_Qe[BB*NN*HH];
__device__ float g_qpool[BB*HH];
__device__ float g_Wqf[HH*(HH+1)];
__device__ float g_WfoldT[HH*HH];
__device__ float g_Wpq[HH*HH];
__device__ float g_M [(size_t)BB*NN*8*NN];  // [b][i][h][n]  (includes C3 fold)
__device__ float g_C2[BB*8*NN];             // [b][h][n]

// ======================= fold kernel =================================
__global__ void fold_kernel(const float* __restrict__ fc_w,
                            const float* __restrict__ fc1_w,
                            const float* __restrict__ Wq,
                            const float* __restrict__ Wo,
                            const float* __restrict__ Wk2)
{
    int mat = blockIdx.y;
    int r   = blockIdx.x;
    int j   = threadIdx.x;
    if (mat == 0) {
        if (j < 129) {
            float acc = 0.f;
            #pragma unroll 8
            for (int i = 0; i < 128; i++) acc += Wq[r*128 + i] * fc_w[i*129 + j];
            g_Wqf[r*129 + j] = 0.25f * acc;
        }
    } else if (mat == 1) {
        if (j < 128) {
            float acc = 0.f;
            #pragma unroll 8
            for (int i = 0; i < 128; i++) acc += Wk2[i*128 + j] * Wo[i*128 + r];
            g_WfoldT[r*128 + j] = (1.0f / sqrtf(128.0f)) * acc;
        }
    } else {
        if (j < 128) {
            float acc = 0.f;
            #pragma unroll 8
            for (int i = 0; i < 128; i++) acc += Wq[r*128 + i] * fc1_w[i*128 + j];
            g_Wpq[r*128 + j] = 0.25f * acc;
        }
    }
}

// ======================= GEMM: out = A @ W^T (FFMA2) ========================
#define GM_TILE 64
#define GEMM_SMEM ((128*132 + GM_TILE*132) * 4)

__global__ __launch_bounds__(256) void gemm_kernel(const float* __restrict__ enc,
                                                   const float* __restrict__ pool,
                                                   const float* __restrict__ Wk,
                                                   const float* __restrict__ Wv)
{
    extern __shared__ float sm[];
    float* sW = sm;
    float* sA = sm + 128*132;

    int slice = blockIdx.y;
    const float* A; const float* W; float* O; int rows; int ldw = 128;
    if      (slice == 0) { A = enc;  W = Wk;       O = g_K;     rows = BB*NN; }
    else if (slice == 1) { A = enc;  W = Wv;       O = g_V;     rows = BB*NN; }
    else if (slice == 2) { A = enc;  W = g_WfoldT; O = g_K2;    rows = BB*NN; }
    else if (slice == 3) { A = enc;  W = g_Wqf;    O = g_Qe;    rows = BB*NN; ldw = 129; }
    else                 { A = pool; W = g_Wpq;    O = g_qpool; rows = BB;    }

    int row0 = blockIdx.x * GM_TILE;
    if (row0 >= rows) return;
    int tid = threadIdx.x;

    for (int i = tid; i < 128*128; i += 256) {
        int c = i >> 7, m = i & 127;
        sW[m*132 + c] = W[c*ldw + m];
    }
    for (int i = tid; i < GM_TILE*128; i += 256) {
        int r = i >> 7, k = i & 127;
        sA[r*132 + k] = A[(row0 + r)*128 + k];
    }
    __syncthreads();

    int warp = tid >> 5, lane = tid & 31;
    int r0 = warp * 8, c0 = lane * 4;

    unsigned long long accp[4][4];
    #pragma unroll
    for (int c = 0; c < 4; c++)
        #pragma unroll
        for (int t = 0; t < 4; t++) PK2(accp[c][t], 0.f, 0.f);

    #pragma unroll 4
    for (int k = 0; k < 128; k++) {
        float4 w4 = *(const float4*)&sW[k*132 + c0];
        unsigned long long wd[4];
        PK2(wd[0], w4.x, w4.x); PK2(wd[1], w4.y, w4.y);
        PK2(wd[2], w4.z, w4.z); PK2(wd[3], w4.w, w4.w);
        unsigned long long ap[4];
        #pragma unroll
        for (int t = 0; t < 4; t++) {
            float a0 = sA[(r0 + 2*t    )*132 + k];
            float a1 = sA[(r0 + 2*t + 1)*132 + k];
            PK2(ap[t], a0, a1);
        }
        #pragma unroll
        for (int c = 0; c < 4; c++)
            #pragma unroll
            for (int t = 0; t < 4; t++) FMA2(accp[c][t], ap[t], wd[c]);
    }

    #pragma unroll
    for (int t = 0; t < 4; t++) {
        float4 v0, v1;
        UPK2(v0.x, v1.x, accp[0][t]);
        UPK2(v0.y, v1.y, accp[1][t]);
        UPK2(v0.z, v1.z, accp[2][t]);
        UPK2(v0.w, v1.w, accp[3][t]);
        *(float4*)&O[(size_t)(row0 + r0 + 2*t    )*128 + c0] = v0;
        *(float4*)&O[(size_t)(row0 + r0 + 2*t + 1)*128 + c0] = v1;
    }
}

// ======================= score precompute ===================================
// M'[b,i,h,n] = dot16(Qe[i,h],K[n,h]) + dot16(qpool_h,K[n,h]);  C2 = dot16(K,Wc)
#define SP_SMEM (NN*128*4)
__global__ __launch_bounds__(256, 2) void score_pre_kernel()
{
    extern __shared__ float sQe[];
    int b = blockIdx.x, tid = threadIdx.x;
    int h = tid >> 5, lane = tid & 31;

    const float* qe = g_Qe + (size_t)b*NN*HH;
    for (int j = tid; j < NN*HH/4; j += 256)
        *(float4*)&sQe[j*4] = ((const float4*)qe)[j];

    float kr[4][16];
    float wc[16], qp[16];
    #pragma unroll
    for (int j = 0; j < 16; j++) {
        wc[j] = g_Wqf[(h*16+j)*129 + 128];
        qp[j] = g_qpool[b*HH + h*16 + j];
    }
    #pragma unroll
    for (int k = 0; k < 4; k++) {
        int n = lane + 32*k;
        if (n < NN) {
            const float* kp = g_K + (size_t)b*NN*HH + (size_t)n*HH + h*16;
            #pragma unroll
            for (int j = 0; j < 16; j += 4) {
                float4 v = *(const float4*)&kp[j];
                kr[k][j]=v.x; kr[k][j+1]=v.y; kr[k][j+2]=v.z; kr[k][j+3]=v.w;
            }
        }
    }
    float a3s[4];
    #pragma unroll
    for (int k = 0; k < 4; k++) {
        int n = lane + 32*k;
        a3s[k] = 0.f;
        if (n < NN) {
            float a2 = 0.f, a3 = 0.f;
            #pragma unroll
            for (int j = 0; j < 16; j++) { a2 += kr[k][j]*wc[j]; a3 += kr[k][j]*qp[j]; }
            g_C2[((size_t)b*8 + h)*NN + n] = a2;
            a3s[k] = a3;
        }
    }
    __syncthreads();

    float* Mb = g_M + (size_t)b*NN*8*NN;
    for (int i = 0; i < NN; i++) {
        float q[16];
        #pragma unroll
        for (int j = 0; j < 16; j += 4) {
            float4 v = *(const float4*)&sQe[i*128 + h*16 + j];
            q[j]=v.x; q[j+1]=v.y; q[j+2]=v.z; q[j+3]=v.w;
        }
        #pragma unroll
        for (int k = 0; k < 4; k++) {
            int n = lane + 32*k;
            if (n < NN) {
                float acc = 0.f;
                #pragma unroll
                for (int j = 0; j < 16; j++) acc += kr[k][j]*q[j];
                Mb[((size_t)i*8 + h)*NN + n] = acc + a3s[k];
            }
        }
    }
}

// ======================= decode kernel ======================================
// smem: sK2 13200 + sAttn 832 + sRden 8 + sPartA 256 + sG 128 + sU 128
//     + sMask 104 + sDem 104 = 14760 floats (~59 KB) -> 3 CTAs/SM
#define DEC_SMEM_FLOATS (NN*NPAD + 832 + 8 + 256 + 128 + 128 + 104 + 104)
#define DEC_SMEM (DEC_SMEM_FLOATS * 4)

__global__ __launch_bounds__(256, 3) void decode_kernel(const float* __restrict__ capacity,
                                                        const float* __restrict__ demand,
                                                        float* __restrict__ out)
{
    extern __shared__ float sm[];
    float* sK2   = sm;                    // [100][132]
    float* sAttn = sK2   + NN*NPAD;       // [8][104] halves at +0/+52 (unnormalized e)
    float* sRden = sAttn + 832;           // [8] 1/sum per head
    float* sPartA= sRden + 8;             // 256
    float* sG    = sPartA+ 256;           // 128
    float* sU    = sG    + 128;           // 128 (pads 100..127 = -inf, never rewritten)
    float* sMask = sU    + 128;           // 104
    float* sDem  = sMask + 104;           // 104

    __shared__ float sCap;
    __shared__ int   sIdx;

    int b = blockIdx.x, tid = threadIdx.x;
    int warp = tid >> 5, lane = tid & 31;
    int d = tid & 127, half = tid >> 7, hh = d >> 4;

    // ---- loads ----
    {
        const float4* gK2 = (const float4*)(g_K2 + (size_t)b*NN*HH);
        for (int j = tid; j < NN*HH/4; j += 256) {
            int n = j >> 5; int c = (j & 31) << 2;
            *(float4*)&sK2[n*NPAD + c] = gK2[j];
        }
    }
    float vreg[50];
    {
        const float* vg = g_V + (size_t)b*NN*HH + (size_t)(half*50)*HH + d;
        #pragma unroll
        for (int i = 0; i < 50; i++) vreg[i] = vg[i*HH];
    }
    if (tid < 100) sDem[tid] = demand[b*NN + tid];
    if (tid >= 100 && tid < 128) sU[tid] = -INFINITY;   // argmax pads (never rewritten)
    if (tid == 0) { sCap = capacity[b]; sIdx = 0; }

    float c2reg[4];
    #pragma unroll
    for (int k = 0; k < 4; k++) {
        int n = lane + 32*k;
        c2reg[k] = (n < 100) ? g_C2[(size_t)b*800 + warp*100 + n] : 0.f;
    }
    float mrow[4];
    {
        const float* mp = g_M + ((size_t)b*NN*8 + warp)*NN;
        #pragma unroll
        for (int k = 0; k < 4; k++) { int n = lane + 32*k; mrow[k] = (n < NN) ? mp[n] : 0.f; }
    }
    __syncthreads();

    const float base_cap = capacity[0];

    // ---- initial mask (index=0, mask1=0, go_depot=1) ----
    if (warp == 0) {
        float cap0 = sCap; int cnt = 0;
        #pragma unroll
        for (int k = 0; k < 4; k++) {
            int n = lane + 32*k;
            if (n >= 1 && n < 100) {
                float m = (sDem[n] > cap0) ? 1.f : 0.f;
                sMask[n] = m;
                if (m == 0.f) cnt++;
            }
        }
        #pragma unroll
        for (int o = 16; o; o >>= 1) cnt += __shfl_xor_sync(0xffffffffu, cnt, o);
        if (lane == 0) sMask[0] = (cnt == 0) ? 0.f : 1.f;
    }
    __syncthreads();

    float logTot = 0.f;
    int   vis    = 0;
    unsigned m1bits = 0;   // warp0: mask1 bits for n = lane + 32k

    for (int s = 0; s < STEPS; s++) {
        // ---- B: e = exp(score) unnormalized; per-head 1/sum ----
        {
            float cap = sCap;
            float e[4]; float sum = 0.f;
            #pragma unroll
            for (int k = 0; k < 4; k++) {
                int n = lane + 32*k;
                float ee = 0.f;
                if (n < 100) {
                    float v = (sMask[n] > 0.f) ? NEGV : fmaf(cap, c2reg[k], mrow[k]);
                    ee = __expf(v);
                }
                e[k] = ee; sum += ee;
            }
            #pragma unroll
            for (int o = 16; o; o >>= 1) sum += __shfl_xor_sync(0xffffffffu, sum, o);
            #pragma unroll
            for (int k = 0; k < 4; k++) {
                int n = lane + 32*k;
                if (n < 100) sAttn[warp*104 + n + ((n >= 50) ? 2 : 0)] = e[k];
            }
            if (lane == 0) sRden[warp] = 1.0f / sum;
        }
        __syncthreads();

        // ---- C: glimpse partials (V in regs, 4 accumulators) ----
        {
            const float* an = sAttn + hh*104 + half*52;
            float a0 = 0.f, a1 = 0.f, a2 = 0.f, a3 = 0.f;
            #pragma unroll
            for (int i = 0; i < 48; i += 4) {
                float4 a4 = *(const float4*)&an[i];
                a0 = fmaf(a4.x, vreg[i],   a0);
                a1 = fmaf(a4.y, vreg[i+1], a1);
                a2 = fmaf(a4.z, vreg[i+2], a2);
                a3 = fmaf(a4.w, vreg[i+3], a3);
            }
            a0 = fmaf(an[48], vreg[48], a0);
            a1 = fmaf(an[49], vreg[49], a1);
            sPartA[tid] = (a0 + a1) + (a2 + a3);
        }
        __syncthreads();

        float uv[4]; float vmax = -INFINITY; int imax = 0;

        // ---- warps 0-3: g-combine (with deferred 1/sum), u, argmax ----
        if (tid < 128) {
            sG[tid] = (sPartA[tid] + sPartA[tid + 128]) * sRden[hh];
            asm volatile("bar.sync 1, 128;" ::: "memory");

            if (tid < 100) {
                const float* kp = sK2 + tid*NPAD;
                float b0 = 0.f, b1 = 0.f, b2 = 0.f, b3 = 0.f;
                #pragma unroll
                for (int j = 0; j < 128; j += 16) {
                    float4 x, g;
                    x = *(const float4*)&kp[j];    g = *(const float4*)&sG[j];
                    b0 = fmaf(x.x,g.x,b0); b0 = fmaf(x.y,g.y,b0); b0 = fmaf(x.z,g.z,b0); b0 = fmaf(x.w,g.w,b0);
                    x = *(const float4*)&kp[j+4];  g = *(const float4*)&sG[j+4];
                    b1 = fmaf(x.x,g.x,b1); b1 = fmaf(x.y,g.y,b1); b1 = fmaf(x.z,g.z,b1); b1 = fmaf(x.w,g.w,b1);
                    x = *(const float4*)&kp[j+8];  g = *(const float4*)&sG[j+8];
                    b2 = fmaf(x.x,g.x,b2); b2 = fmaf(x.y,g.y,b2); b2 = fmaf(x.z,g.z,b2); b2 = fmaf(x.w,g.w,b2);
                    x = *(const float4*)&kp[j+12]; g = *(const float4*)&sG[j+12];
                    b3 = fmaf(x.x,g.x,b3); b3 = fmaf(x.y,g.y,b3); b3 = fmaf(x.z,g.z,b3); b3 = fmaf(x.w,g.w,b3);
                }
                float t = (b0 + b1) + (b2 + b3);
                sU[tid] = (sMask[tid] > 0.f) ? NEGV : 10.0f * tanhf(t);
            }
            asm volatile("bar.sync 1, 128;" ::: "memory");

            // warp0: argmax + publish sIdx ASAP (sU pads 100..127 are -inf)
            if (warp == 0) {
                #pragma unroll
                for (int k = 0; k < 4; k++) uv[k] = sU[lane + 32*k];
                #pragma unroll
                for (int k = 0; k < 4; k++) {
                    int n = lane + 32*k;
                    if (uv[k] > vmax) { vmax = uv[k]; imax = n; }
                }
                #pragma unroll
                for (int o = 16; o; o >>= 1) {
                    float ov = __shfl_down_sync(0xffffffffu, vmax, o);
                    int   oi = __shfl_down_sync(0xffffffffu, imax, o);
                    if (ov > vmax || (ov == vmax && oi < imax)) { vmax = ov; imax = oi; }
                }
                vmax = __shfl_sync(0xffffffffu, vmax, 0);
                imax = __shfl_sync(0xffffffffu, imax, 0);
                if (lane == 0) sIdx = imax;
            }
        }
        __syncthreads();   // publish sIdx

        // ---- ALL warps: prefetch next M row early (hides DRAM under E-tail) ----
        {
            int idx = sIdx;
            const float* mp = g_M + (((size_t)b*NN + idx)*8 + warp)*NN;
            #pragma unroll
            for (int k = 0; k < 4; k++) { int n = lane + 32*k; if (n < NN) mrow[k] = mp[n]; }
        }

        // ---- warp0 tail: logp, state, mask (overlaps M prefetch latency) ----
        if (warp == 0) {
            float sum = 0.f;
            #pragma unroll
            for (int k = 0; k < 4; k++) {
                int n = lane + 32*k;
                if (n < 100) sum += __expf(uv[k] - vmax);
            }
            #pragma unroll
            for (int o = 16; o; o >>= 1) sum += __shfl_xor_sync(0xffffffffu, sum, o);

            float capNew = 0.f;
            if (lane == 0) {
                float logp = -logf(sum);
                if (vis < 99) logTot += logp;
                out[(size_t)b*STEPS + s] = (float)imax;
                float seld = sDem[imax];
                capNew = (imax == 0) ? base_cap : (sCap - seld);
                sCap = capNew;
            }
            capNew = __shfl_sync(0xffffffffu, capNew, 0);

            // mask1 (bits) + vis
            int kbit = imax >> 5;
            int owner = (lane == (imax & 31));
            unsigned newly = (owner && imax > 0 && !((m1bits >> kbit) & 1u)) ? 1u : 0u;
            unsigned bal = __ballot_sync(0xffffffffu, newly);
            if (bal) vis += 1;
            if (owner && imax > 0) m1bits |= (1u << kbit);

            int goDepot = (imax == 0);
            int cnt = 0;
            #pragma unroll
            for (int k = 0; k < 4; k++) {
                int n = lane + 32*k;
                if (n >= 1 && n < 100) {
                    float m1v = ((m1bits >> k) & 1u) ? 1.f : 0.f;
                    float m = fmaxf(m1v, (sDem[n] > capNew) ? 1.f : 0.f);
                    sMask[n] = m;
                    if (m == 0.f) cnt++;
                }
            }
            #pragma unroll
            for (int o = 16; o; o >>= 1) cnt += __shfl_xor_sync(0xffffffffu, cnt, o);
            if (lane == 0) sMask[0] = (cnt == 0) ? 0.f : (goDepot ? 1.f : 0.f);
        }
        __syncthreads();
    }

    if (tid == 0) out[(size_t)BB*STEPS + b] = logTot;
}

// ======================= launcher ===========================================
extern "C" void kernel_launch(void* const* d_in, const int* in_sizes, int n_in,
                              void* d_out, int out_size)
{
    const float* enc      = (const float*)d_in[0];
    const float* pool     = (const float*)d_in[1];
    const float* capacity = (const float*)d_in[2];
    const float* demand   = (const float*)d_in[3];
    const float* fc_w     = (const float*)d_in[4];
    const float* fc1_w    = (const float*)d_in[5];
    const float* Wq       = (const float*)d_in[6];
    const float* Wk       = (const float*)d_in[7];
    const float* Wv       = (const float*)d_in[8];
    const float* Wo       = (const float*)d_in[9];
    const float* Wk2      = (const float*)d_in[10];
    float* out = (float*)d_out;

    cudaFuncSetAttribute(gemm_kernel,      cudaFuncAttributeMaxDynamicSharedMemorySize, GEMM_SMEM);
    cudaFuncSetAttribute(score_pre_kernel, cudaFuncAttributeMaxDynamicSharedMemorySize, SP_SMEM);
    cudaFuncSetAttribute(decode_kernel,    cudaFuncAttributeMaxDynamicSharedMemorySize, DEC_SMEM);

    fold_kernel<<<dim3(128, 3), 132>>>(fc_w, fc1_w, Wq, Wo, Wk2);
    gemm_kernel<<<dim3((BB*NN)/GM_TILE, 5), 256, GEMM_SMEM>>>(enc, pool, Wk, Wv);
    score_pre_kernel<<<BB, 256, SP_SMEM>>>();
    decode_kernel<<<BB, 256, DEC_SMEM>>>(capacity, demand, out);
}